// round 1
// baseline (speedup 1.0000x reference)
#include <cuda_runtime.h>
#include <math.h>

#define NHEADS 16
#define DK     64
#define DM     1024
#define NB     2
#define SEQ    2048
#define MTOT   (NB*SEQ)   /* 4096 */

// Scratch (allocation-free rule: __device__ globals)
static __device__ float g_Q [(size_t)MTOT*DM];
static __device__ float g_K [(size_t)MTOT*DM];
static __device__ float g_V [(size_t)MTOT*DM];
static __device__ float g_Hc[(size_t)MTOT*DM];

// ---------------------------------------------------------------------------
// Generic batched tiled GEMM: C = A @ B (+bias)
// Tile: BM=BN=64, BK=16. 256 threads, each computes a 4x4 micro-tile.
// Batch index z decomposes as (outer, inner) with inner count Hn, so one
// kernel serves unbatched projections (Hn=1) and the per-(b,h) AV GEMM.
// All problem dims are multiples of 64/16 -> no bounds checks.
// ---------------------------------------------------------------------------
__global__ __launch_bounds__(256) void gemm64(
    const float* __restrict__ A, int lda, long long sAb, long long sAh,
    const float* __restrict__ B, int ldb, long long sBb, long long sBh,
    float*       __restrict__ C, int ldc, long long sCb, long long sCh,
    int K, const float* __restrict__ bias, int Hn)
{
    const int bz = blockIdx.z;
    const int bo = bz / Hn;
    const int hi = bz - bo * Hn;
    A += (long long)bo * sAb + (long long)hi * sAh;
    B += (long long)bo * sBb + (long long)hi * sBh;
    C += (long long)bo * sCb + (long long)hi * sCh;

    const int m0 = blockIdx.y * 64;
    const int n0 = blockIdx.x * 64;

    __shared__ float As[16][65];   // transposed A tile, padded (conflict-free stores)
    __shared__ float Bs[16][64];   // natural B tile (vectorized stores)

    const int tid = threadIdx.x;
    const int tx  = tid & 15;          // 0..15 -> N micro col
    const int ty  = tid >> 4;          // 0..15 -> M micro row
    const int ar  = tid >> 2;          // A-load row   0..63
    const int ac  = (tid & 3) << 2;    // A-load col0  {0,4,8,12}
    const int br  = tid >> 4;          // B-load row   0..15
    const int bc  = (tid & 15) << 2;   // B-load col0

    float acc[4][4] = {};

    for (int k0 = 0; k0 < K; k0 += 16) {
        const float4 av = *reinterpret_cast<const float4*>(
            &A[(long long)(m0 + ar) * lda + k0 + ac]);
        const float4 bv = *reinterpret_cast<const float4*>(
            &B[(long long)(k0 + br) * ldb + n0 + bc]);

        __syncthreads();   // previous iteration's compute done
        As[ac + 0][ar] = av.x;
        As[ac + 1][ar] = av.y;
        As[ac + 2][ar] = av.z;
        As[ac + 3][ar] = av.w;
        *reinterpret_cast<float4*>(&Bs[br][bc]) = bv;
        __syncthreads();   // tiles visible

        #pragma unroll
        for (int kk = 0; kk < 16; ++kk) {
            float ra[4], rb[4];
            #pragma unroll
            for (int i = 0; i < 4; ++i) ra[i] = As[kk][ty * 4 + i];
            #pragma unroll
            for (int j = 0; j < 4; ++j) rb[j] = Bs[kk][tx * 4 + j];
            #pragma unroll
            for (int i = 0; i < 4; ++i)
                #pragma unroll
                for (int j = 0; j < 4; ++j)
                    acc[i][j] = fmaf(ra[i], rb[j], acc[i][j]);
        }
    }

    #pragma unroll
    for (int i = 0; i < 4; ++i) {
        const int row = m0 + ty * 4 + i;
        #pragma unroll
        for (int j = 0; j < 4; ++j) {
            const int col = n0 + tx * 4 + j;
            float v = acc[i][j];
            if (bias) v += bias[col];
            C[(long long)row * ldc + col] = v;
        }
    }
}

// ---------------------------------------------------------------------------
// Scores + sigmoid: A[b,h,q,k] = sigmoid( (Q[b,h,q,:] . K[b,h,k,:]) / 8 )
// dk = 64 fits entirely in smem -> single K pass. 64x64 output tile / block.
// ---------------------------------------------------------------------------
__global__ __launch_bounds__(256) void scores_kernel(float* __restrict__ Aout)
{
    const int bh = blockIdx.z;
    const int b  = bh >> 4;
    const int h  = bh & 15;
    const float* Qb = g_Q + (long long)b * SEQ * DM + h * DK;
    const float* Kb = g_K + (long long)b * SEQ * DM + h * DK;

    const int q0 = blockIdx.y * 64;
    const int k0 = blockIdx.x * 64;

    __shared__ float Qs[64][65];   // [d][q], padded
    __shared__ float Ks[64][65];   // [d][k], padded

    const int tid = threadIdx.x;
    const int tx  = tid & 15;
    const int ty  = tid >> 4;
    const int lr  = tid >> 2;          // row 0..63
    const int lc  = (tid & 3) << 2;    // d-col0 {0,4,8,12}

    #pragma unroll
    for (int s = 0; s < 4; ++s) {
        const int d0 = s * 16;
        const float4 qv = *reinterpret_cast<const float4*>(
            &Qb[(long long)(q0 + lr) * DM + d0 + lc]);
        const float4 kv = *reinterpret_cast<const float4*>(
            &Kb[(long long)(k0 + lr) * DM + d0 + lc]);
        Qs[d0 + lc + 0][lr] = qv.x;  Qs[d0 + lc + 1][lr] = qv.y;
        Qs[d0 + lc + 2][lr] = qv.z;  Qs[d0 + lc + 3][lr] = qv.w;
        Ks[d0 + lc + 0][lr] = kv.x;  Ks[d0 + lc + 1][lr] = kv.y;
        Ks[d0 + lc + 2][lr] = kv.z;  Ks[d0 + lc + 3][lr] = kv.w;
    }
    __syncthreads();

    float acc[4][4] = {};
    #pragma unroll 16
    for (int d = 0; d < 64; ++d) {
        float rq[4], rk[4];
        #pragma unroll
        for (int i = 0; i < 4; ++i) rq[i] = Qs[d][ty * 4 + i];
        #pragma unroll
        for (int j = 0; j < 4; ++j) rk[j] = Ks[d][tx * 4 + j];
        #pragma unroll
        for (int i = 0; i < 4; ++i)
            #pragma unroll
            for (int j = 0; j < 4; ++j)
                acc[i][j] = fmaf(rq[i], rk[j], acc[i][j]);
    }

    #pragma unroll
    for (int i = 0; i < 4; ++i) {
        const long long q = q0 + ty * 4 + i;
        float* rowp = Aout + ((long long)bh * SEQ + q) * SEQ + k0;
        #pragma unroll
        for (int j = 0; j < 4; ++j) {
            const float sc  = acc[i][j] * 0.125f;            // 1/sqrt(64)
            rowp[tx * 4 + j] = 1.0f / (1.0f + expf(-sc));     // sigmoid
        }
    }
}

// ---------------------------------------------------------------------------
extern "C" void kernel_launch(void* const* d_in, const int* in_sizes, int n_in,
                              void* d_out, int out_size)
{
    (void)in_sizes; (void)n_in; (void)out_size;
    const float* Xq = (const float*)d_in[0];
    const float* Xk = (const float*)d_in[1];
    const float* Xv = (const float*)d_in[2];
    const float* Wq = (const float*)d_in[3];
    const float* Wk = (const float*)d_in[4];
    const float* Wv = (const float*)d_in[5];
    const float* Wh = (const float*)d_in[6];
    const float* bh = (const float*)d_in[7];

    float* out  = (float*)d_out;
    float* Aout = out + (long long)MTOT * DM;   // [B,H,S,S] after H_out [B,S,D]

    float *qp, *kp, *vp, *hp;
    cudaGetSymbolAddress((void**)&qp, g_Q);
    cudaGetSymbolAddress((void**)&kp, g_K);
    cudaGetSymbolAddress((void**)&vp, g_V);
    cudaGetSymbolAddress((void**)&hp, g_Hc);

    const dim3 thr(256);

    // 1) Q/K/V projections: [4096,1024] @ [1024,1024]
    const dim3 gProj(DM / 64, MTOT / 64, 1);
    gemm64<<<gProj, thr>>>(Xq, DM, 0, 0,  Wq, DM, 0, 0,  qp, DM, 0, 0,
                           DM, nullptr, 1);
    gemm64<<<gProj, thr>>>(Xk, DM, 0, 0,  Wk, DM, 0, 0,  kp, DM, 0, 0,
                           DM, nullptr, 1);
    gemm64<<<gProj, thr>>>(Xv, DM, 0, 0,  Wv, DM, 0, 0,  vp, DM, 0, 0,
                           DM, nullptr, 1);

    // 2) scores + sigmoid -> A (second output region)
    const dim3 gSc(SEQ / 64, SEQ / 64, NB * NHEADS);
    scores_kernel<<<gSc, thr>>>(Aout);

    // 3) H = A @ V per (b,h): [2048,2048] @ [2048,64] -> Hcat[B,S,D]
    const dim3 gAV(1, SEQ / 64, NB * NHEADS);
    gemm64<<<gAV, thr>>>(Aout, SEQ, (long long)NHEADS * SEQ * SEQ, (long long)SEQ * SEQ,
                         vp,   DM,  (long long)SEQ * DM,           (long long)DK,
                         hp,   DM,  (long long)SEQ * DM,           (long long)DK,
                         SEQ, nullptr, NHEADS);

    // 4) H_out = Hcat @ W_hidden + b_hidden  (first output region)
    gemm64<<<gProj, thr>>>(hp, DM, 0, 0,  Wh, DM, 0, 0,  out, DM, 0, 0,
                           DM, bh, 1);
}

// round 3
// speedup vs baseline: 1.9453x; 1.9453x over previous
#include <cuda_runtime.h>
#include <cuda_bf16.h>
#include <cstdint>
#include <math.h>

#define NHEADS 16
#define DK     64
#define DM     1024
#define NB     2
#define SEQ    2048
#define MTOT   (NB*SEQ)   /* 4096 */

// fp32 scratch (allocation-free rule: __device__ globals)
static __device__ float g_Q [(size_t)MTOT*DM];
static __device__ float g_K [(size_t)MTOT*DM];
static __device__ float g_V [(size_t)MTOT*DM];
static __device__ float g_Hc[(size_t)MTOT*DM];
static __device__ float g_Wt[4][(size_t)DM*DM];          // W^T for q,k,v,hidden
static __device__ float g_Vt[(size_t)NB*NHEADS*DK*SEQ];  // V^T per (b,h): [dk][seq]

__device__ __forceinline__ uint32_t smem_u32(const void* p) {
    uint32_t a;
    asm("{ .reg .u64 t; cvta.to.shared.u64 t, %1; cvt.u32.u64 %0, t; }"
        : "=r"(a) : "l"(p));
    return a;
}

#define LDSM4(d, addr) \
    asm volatile("ldmatrix.sync.aligned.m8n8.x4.shared.b16 {%0,%1,%2,%3}, [%4];" \
        : "=r"((d)[0]), "=r"((d)[1]), "=r"((d)[2]), "=r"((d)[3]) : "r"(addr))

#define MMA_BF16(c, a, b0v, b1v) \
    asm volatile("mma.sync.aligned.m16n8k16.row.col.f32.bf16.bf16.f32 " \
        "{%0,%1,%2,%3},{%4,%5,%6,%7},{%8,%9},{%0,%1,%2,%3};" \
        : "+f"((c)[0]), "+f"((c)[1]), "+f"((c)[2]), "+f"((c)[3]) \
        : "r"((a)[0]), "r"((a)[1]), "r"((a)[2]), "r"((a)[3]), "r"(b0v), "r"(b1v))

// fp32 quad -> bf16 hi (RN) + bf16 lo (residual), 8B each
__device__ __forceinline__ void cvt_store(const float4 v, char* hip, char* lop) {
    __nv_bfloat16 h0 = __float2bfloat16(v.x), h1 = __float2bfloat16(v.y),
                  h2 = __float2bfloat16(v.z), h3 = __float2bfloat16(v.w);
    __nv_bfloat16 l0 = __float2bfloat16(v.x - __bfloat162float(h0));
    __nv_bfloat16 l1 = __float2bfloat16(v.y - __bfloat162float(h1));
    __nv_bfloat16 l2 = __float2bfloat16(v.z - __bfloat162float(h2));
    __nv_bfloat16 l3 = __float2bfloat16(v.w - __bfloat162float(h3));
    __nv_bfloat162 ha(h0, h1), hb(h2, h3), la(l0, l1), lb(l2, l3);
    *reinterpret_cast<uint2*>(hip) =
        make_uint2(*reinterpret_cast<uint32_t*>(&ha), *reinterpret_cast<uint32_t*>(&hb));
    *reinterpret_cast<uint2*>(lop) =
        make_uint2(*reinterpret_cast<uint32_t*>(&la), *reinterpret_cast<uint32_t*>(&lb));
}

// ---------------------------------------------------------------------------
// bf16-split GEMM via mma.sync: C[M,N] = A[M,K] @ B[N,K]^T  (fp32 in/out)
// BM=128, BN in {128,64}, BK=32 fp32. 256 threads, 8 warps.
// 3 passes per k-slab: Ahi*Bhi + Ahi*Blo + Alo*Bhi (fp32 accum).
// EPI: 0 = plain store, 1 = sigmoid(v/8), 2 = v + bias.
// ---------------------------------------------------------------------------
template<int BN, int EPI>
__global__ __launch_bounds__(256) void hgemm(
    const float* __restrict__ Asrc, long long aB, long long aH, int lda,
    const float* __restrict__ Bsrc, long long bB, long long bH, int ldb,
    float*       __restrict__ Cf,   long long cB, long long cH, int ldc,
    const float* __restrict__ bias, int K, int Hn)
{
    extern __shared__ char sm[];
    constexpr int BM = 128;
    constexpr int WM = (BN == 128) ? 64 : 32;
    constexpr int WN = 32;
    constexpr int MWARPS = BM / WM;
    constexpr int MG = WM / 16, NP = WN / 16;
    constexpr int AST = 40;                       // bf16 row stride (80B, padded)
    constexpr int ASZ = BM * AST * 2;
    constexpr int BSZ = BN * AST * 2;
    constexpr int BUF = 2 * ASZ + 2 * BSZ;
    constexpr int BPASS = BN / 32;

    const int tid = threadIdx.x, lane = tid & 31, wid = tid >> 5;
    const int wm0 = (wid % MWARPS) * WM;
    const int wn0 = (wid / MWARPS) * WN;

    const int z = blockIdx.z, bo = z / Hn, hh = z - bo * Hn;
    Asrc += bo * aB + (long long)hh * aH;
    Bsrc += bo * bB + (long long)hh * bH;
    Cf   += bo * cB + (long long)hh * cH;

    const int m0 = blockIdx.y * BM;
    const int n0 = blockIdx.x * BN;
    const float* Ag = Asrc + (long long)m0 * lda;
    const float* Bg = Bsrc + (long long)n0 * ldb;

    const uint32_t sbase = smem_u32(sm);
    const int NC = K / 32;

    float4 sa[4], sb[BPASS];
    const int lr = tid >> 3;            // load row 0..31 (per pass)
    const int lc = (tid & 7) * 4;       // fp32 col

    auto ldg = [&](int c) {
        const float* ap = Ag + (long long)lr * lda + c * 32 + lc;
        #pragma unroll
        for (int p = 0; p < 4; ++p) sa[p] = *(const float4*)(ap + (long long)p * 32 * lda);
        const float* bp = Bg + (long long)lr * ldb + c * 32 + lc;
        #pragma unroll
        for (int p = 0; p < BPASS; ++p) sb[p] = *(const float4*)(bp + (long long)p * 32 * ldb);
    };
    auto sts = [&](int b) {
        char* base = sm + b * BUF;
        #pragma unroll
        for (int p = 0; p < 4; ++p) {
            const int off = ((lr + p * 32) * AST + lc) * 2;
            cvt_store(sa[p], base + off, base + ASZ + off);
        }
        char* bb = base + 2 * ASZ;
        #pragma unroll
        for (int p = 0; p < BPASS; ++p) {
            const int off = ((lr + p * 32) * AST + lc) * 2;
            cvt_store(sb[p], bb + off, bb + BSZ + off);
        }
    };

    float acc[MG][NP][2][4] = {};
    const int frow = lane & 15;         // ldmatrix row within 16
    const int fk8  = (lane >> 4) * 8;   // ldmatrix k-offset

    auto comp = [&](int b) {
        const uint32_t s0 = sbase + b * BUF;
        #pragma unroll
        for (int slab = 0; slab < 2; ++slab) {
            uint32_t a_h[MG][4], a_l[MG][4], b_h[NP][4], b_l[NP][4];
            #pragma unroll
            for (int mg = 0; mg < MG; ++mg) {
                const uint32_t off = ((wm0 + mg * 16 + frow) * AST + slab * 16 + fk8) * 2;
                LDSM4(a_h[mg], s0 + off);
                LDSM4(a_l[mg], s0 + ASZ + off);
            }
            #pragma unroll
            for (int np = 0; np < NP; ++np) {
                const uint32_t off = ((wn0 + np * 16 + frow) * AST + slab * 16 + fk8) * 2;
                LDSM4(b_h[np], s0 + 2 * ASZ + off);
                LDSM4(b_l[np], s0 + 2 * ASZ + BSZ + off);
            }
            // pass-major: same accumulator reused only every MG*NP*2 MMAs
            #pragma unroll
            for (int pass = 0; pass < 3; ++pass) {
                #pragma unroll
                for (int mg = 0; mg < MG; ++mg)
                    #pragma unroll
                    for (int np = 0; np < NP; ++np)
                        #pragma unroll
                        for (int g = 0; g < 2; ++g) {
                            const uint32_t* av = (pass == 2) ? a_l[mg] : a_h[mg];
                            const uint32_t* bv = (pass == 1) ? b_l[np] : b_h[np];
                            MMA_BF16(acc[mg][np][g], av, bv[g], bv[g + 2]);
                        }
            }
        }
    };

    // pipeline: ldg(0); sts(0); loop
    ldg(0);
    sts(0);
    for (int c = 0; c < NC; ++c) {
        __syncthreads();
        if (c + 1 < NC) ldg(c + 1);
        comp(c & 1);
        if (c + 1 < NC) {
            __syncthreads();
            sts((c + 1) & 1);
        }
    }

    // epilogue: c0,c1 -> (row, col..col+1); c2,c3 -> (row+8, ...)
    #pragma unroll
    for (int mg = 0; mg < MG; ++mg) {
        const int row = m0 + wm0 + mg * 16 + (lane >> 2);
        #pragma unroll
        for (int np = 0; np < NP; ++np)
            #pragma unroll
            for (int g = 0; g < 2; ++g) {
                const int col = n0 + wn0 + np * 16 + g * 8 + (lane & 3) * 2;
                float v0 = acc[mg][np][g][0], v1 = acc[mg][np][g][1];
                float v2 = acc[mg][np][g][2], v3 = acc[mg][np][g][3];
                if (EPI == 1) {
                    v0 = 1.0f / (1.0f + __expf(-0.125f * v0));
                    v1 = 1.0f / (1.0f + __expf(-0.125f * v1));
                    v2 = 1.0f / (1.0f + __expf(-0.125f * v2));
                    v3 = 1.0f / (1.0f + __expf(-0.125f * v3));
                } else if (EPI == 2) {
                    const float b0 = bias[col], b1 = bias[col + 1];
                    v0 += b0; v1 += b1; v2 += b0; v3 += b1;
                }
                *reinterpret_cast<float2*>(Cf + (long long)row * ldc + col) =
                    make_float2(v0, v1);
                *reinterpret_cast<float2*>(Cf + (long long)(row + 8) * ldc + col) =
                    make_float2(v2, v3);
            }
    }
}

// ---------------------------------------------------------------------------
// Transposes (dst[n][k] = src[k][n]) so all MMA operands are K-major.
// ---------------------------------------------------------------------------
__global__ void transpose_sq(const float* __restrict__ src, float* __restrict__ dst, int N)
{
    __shared__ float t[32][33];
    int x = blockIdx.x * 32 + threadIdx.x;
    int y = blockIdx.y * 32 + threadIdx.y;
    #pragma unroll
    for (int j = 0; j < 32; j += 8)
        t[threadIdx.y + j][threadIdx.x] = src[(long long)(y + j) * N + x];
    __syncthreads();
    x = blockIdx.y * 32 + threadIdx.x;
    y = blockIdx.x * 32 + threadIdx.y;
    #pragma unroll
    for (int j = 0; j < 32; j += 8)
        dst[(long long)(y + j) * N + x] = t[threadIdx.x][threadIdx.y + j];
}

__global__ void vtrans(const float* __restrict__ V, float* __restrict__ Vt)
{
    __shared__ float t[32][33];
    const int bh = blockIdx.z, b = bh >> 4, h = bh & 15;
    const int s0 = blockIdx.x * 32, d0 = blockIdx.y * 32;
    const float* src = V + ((long long)b * SEQ) * DM + h * DK;
    #pragma unroll
    for (int j = 0; j < 32; j += 8)
        t[threadIdx.y + j][threadIdx.x] =
            src[(long long)(s0 + threadIdx.y + j) * DM + d0 + threadIdx.x];
    __syncthreads();
    float* dst = Vt + (long long)bh * DK * SEQ;
    #pragma unroll
    for (int j = 0; j < 32; j += 8)
        dst[(long long)(d0 + threadIdx.y + j) * SEQ + s0 + threadIdx.x] =
            t[threadIdx.x][threadIdx.y + j];
}

// ---------------------------------------------------------------------------
static inline int smem_for(int BN) {
    const int ASZ = 128 * 40 * 2, BSZ = BN * 40 * 2;
    return 2 * (2 * ASZ + 2 * BSZ);
}

extern "C" void kernel_launch(void* const* d_in, const int* in_sizes, int n_in,
                              void* d_out, int out_size)
{
    (void)in_sizes; (void)n_in; (void)out_size;
    const float* Xq = (const float*)d_in[0];
    const float* Xk = (const float*)d_in[1];
    const float* Xv = (const float*)d_in[2];
    const float* Wq = (const float*)d_in[3];
    const float* Wk = (const float*)d_in[4];
    const float* Wv = (const float*)d_in[5];
    const float* Wh = (const float*)d_in[6];
    const float* bh = (const float*)d_in[7];

    float* out  = (float*)d_out;
    float* Aout = out + (long long)MTOT * DM;   // [B,H,S,S] after H_out [B,S,D]

    float *qp, *kp, *vp, *hp, *wt, *vt;
    cudaGetSymbolAddress((void**)&qp, g_Q);
    cudaGetSymbolAddress((void**)&kp, g_K);
    cudaGetSymbolAddress((void**)&vp, g_V);
    cudaGetSymbolAddress((void**)&hp, g_Hc);
    cudaGetSymbolAddress((void**)&wt, g_Wt);
    cudaGetSymbolAddress((void**)&vt, g_Vt);
    float* wtq = wt;
    float* wtk = wt + (size_t)DM * DM;
    float* wtv = wt + 2 * (size_t)DM * DM;
    float* wth = wt + 3 * (size_t)DM * DM;

    const int sm128 = smem_for(128);   // 81920
    const int sm64  = smem_for(64);    // 61440
    cudaFuncSetAttribute(hgemm<128, 0>, cudaFuncAttributeMaxDynamicSharedMemorySize, sm128);
    cudaFuncSetAttribute(hgemm<128, 1>, cudaFuncAttributeMaxDynamicSharedMemorySize, sm128);
    cudaFuncSetAttribute(hgemm<128, 2>, cudaFuncAttributeMaxDynamicSharedMemorySize, sm128);
    cudaFuncSetAttribute(hgemm<64, 0>,  cudaFuncAttributeMaxDynamicSharedMemorySize, sm64);

    const dim3 tb(32, 8);
    // 0) weight transposes
    transpose_sq<<<dim3(32, 32), tb>>>(Wq, wtq, DM);
    transpose_sq<<<dim3(32, 32), tb>>>(Wk, wtk, DM);
    transpose_sq<<<dim3(32, 32), tb>>>(Wv, wtv, DM);
    transpose_sq<<<dim3(32, 32), tb>>>(Wh, wth, DM);

    // 1) projections: [4096,1024] = X @ W  (B operand = W^T, K-major)
    const dim3 gP(DM / 128, MTOT / 128, 1);
    hgemm<128, 0><<<gP, 256, sm128>>>(
        Xq, 0, 0, DM,  wtq, 0, 0, DM,  qp, 0, 0, DM,  nullptr, DM, 1);
    hgemm<128, 0><<<gP, 256, sm128>>>(
        Xk, 0, 0, DM,  wtk, 0, 0, DM,  kp, 0, 0, DM,  nullptr, DM, 1);
    hgemm<128, 0><<<gP, 256, sm128>>>(
        Xv, 0, 0, DM,  wtv, 0, 0, DM,  vp, 0, 0, DM,  nullptr, DM, 1);

    // 2) scores + sigmoid: A[bh,q,k] = sigmoid(Q.K/8)
    const dim3 gS(SEQ / 128, SEQ / 128, NB * NHEADS);
    hgemm<128, 1><<<gS, 256, sm128>>>(
        qp, (long long)SEQ * DM, DK, DM,
        kp, (long long)SEQ * DM, DK, DM,
        Aout, (long long)NHEADS * SEQ * SEQ, (long long)SEQ * SEQ, SEQ,
        nullptr, DK, NHEADS);

    // 3) V^T for AV
    vtrans<<<dim3(SEQ / 32, DK / 32, NB * NHEADS), tb>>>(vp, vt);

    // 4) H = A @ V per (b,h): [2048,2048] x [2048,64]
    const dim3 gAV(1, SEQ / 128, NB * NHEADS);
    hgemm<64, 0><<<gAV, 256, sm64>>>(
        Aout, (long long)NHEADS * SEQ * SEQ, (long long)SEQ * SEQ, SEQ,
        vt, (long long)NHEADS * DK * SEQ, (long long)DK * SEQ, SEQ,
        hp, (long long)SEQ * DM, DK, DM,
        nullptr, SEQ, NHEADS);

    // 5) H_out = Hc @ W_hidden + b
    hgemm<128, 2><<<gP, 256, sm128>>>(
        hp, 0, 0, DM,  wth, 0, 0, DM,  out, 0, 0, DM,  bh, DM, 1);
}

// round 4
// speedup vs baseline: 2.0739x; 1.0661x over previous
#include <cuda_runtime.h>
#include <cuda_bf16.h>
#include <cstdint>
#include <math.h>

#define NHEADS 16
#define DK     64
#define DM     1024
#define NB     2
#define SEQ    2048
#define MTOT   (NB*SEQ)   /* 4096 */
#define NBH    (NB*NHEADS)

typedef __nv_bfloat16 bf16;

// scratch (__device__ globals; no allocs allowed)
static __device__ float g_V [(size_t)MTOT*DM];                 // V fp32 (for transpose)
static __device__ bf16  g_Xh[3][(size_t)MTOT*DM];              // X hi (q,k,v)
static __device__ bf16  g_Xl[3][(size_t)MTOT*DM];
static __device__ bf16  g_Wh[4][(size_t)DM*DM];                // W^T hi (q,k,v,hidden)
static __device__ bf16  g_Wl[4][(size_t)DM*DM];
static __device__ bf16  g_Qh[(size_t)NBH*SEQ*DK], g_Ql[(size_t)NBH*SEQ*DK];
static __device__ bf16  g_Kh[(size_t)NBH*SEQ*DK], g_Kl[(size_t)NBH*SEQ*DK];
static __device__ bf16  g_Vth[(size_t)NBH*DK*SEQ], g_Vtl[(size_t)NBH*DK*SEQ];
static __device__ bf16  g_Hh[(size_t)MTOT*DM],    g_Hl[(size_t)MTOT*DM];

// ---------------------------------------------------------------------------
__device__ __forceinline__ uint32_t smem_u32(const void* p) {
    uint32_t a;
    asm("{ .reg .u64 t; cvta.to.shared.u64 t, %1; cvt.u32.u64 %0, t; }"
        : "=r"(a) : "l"(p));
    return a;
}
#define CP16(dst, src) \
    asm volatile("cp.async.cg.shared.global [%0], [%1], 16;" \
        :: "r"(dst), "l"(src) : "memory")
#define CPCOMMIT() asm volatile("cp.async.commit_group;" ::: "memory")
#define CPWAIT(n)  asm volatile("cp.async.wait_group %0;" :: "n"(n) : "memory")

#define LDSM4(d, addr) \
    asm volatile("ldmatrix.sync.aligned.m8n8.x4.shared.b16 {%0,%1,%2,%3}, [%4];" \
        : "=r"((d)[0]), "=r"((d)[1]), "=r"((d)[2]), "=r"((d)[3]) : "r"(addr))

#define MMA_BF16(c, a, b0v, b1v) \
    asm volatile("mma.sync.aligned.m16n8k16.row.col.f32.bf16.bf16.f32 " \
        "{%0,%1,%2,%3},{%4,%5,%6,%7},{%8,%9},{%0,%1,%2,%3};" \
        : "+f"((c)[0]), "+f"((c)[1]), "+f"((c)[2]), "+f"((c)[3]) \
        : "r"((a)[0]), "r"((a)[1]), "r"((a)[2]), "r"((a)[3]), "r"(b0v), "r"(b1v))

// split (e0,e1) fp32 -> packed bf16x2 hi + packed bf16x2 lo (low half = e0)
__device__ __forceinline__ void split2(float e0, float e1, uint32_t& h, uint32_t& l) {
    bf16 h0 = __float2bfloat16(e0), h1 = __float2bfloat16(e1);
    bf16 l0 = __float2bfloat16(e0 - __bfloat162float(h0));
    bf16 l1 = __float2bfloat16(e1 - __bfloat162float(h1));
    __nv_bfloat162 hh(h0, h1), ll(l0, l1);
    h = *reinterpret_cast<uint32_t*>(&hh);
    l = *reinterpret_cast<uint32_t*>(&ll);
}

// ---------------------------------------------------------------------------
// small prep kernels
// ---------------------------------------------------------------------------
__global__ void split_x(const float4* __restrict__ src,
                        uint2* __restrict__ dh, uint2* __restrict__ dl)
{
    const int i = blockIdx.x * 256 + threadIdx.x;
    const float4 v = src[i];
    uint2 H, L;
    split2(v.x, v.y, H.x, L.x);
    split2(v.z, v.w, H.y, L.y);
    dh[i] = H; dl[i] = L;
}

__global__ void transpose_split(const float* __restrict__ src,
                                bf16* __restrict__ dh, bf16* __restrict__ dl, int N)
{
    __shared__ float t[32][33];
    int x = blockIdx.x * 32 + threadIdx.x;
    int y = blockIdx.y * 32 + threadIdx.y;
    #pragma unroll
    for (int j = 0; j < 32; j += 8)
        t[threadIdx.y + j][threadIdx.x] = src[(long long)(y + j) * N + x];
    __syncthreads();
    x = blockIdx.y * 32 + threadIdx.x;
    y = blockIdx.x * 32 + threadIdx.y;
    #pragma unroll
    for (int j = 0; j < 32; j += 8) {
        const float v = t[threadIdx.x][threadIdx.y + j];
        bf16 h = __float2bfloat16(v);
        dh[(long long)(y + j) * N + x] = h;
        dl[(long long)(y + j) * N + x] = __float2bfloat16(v - __bfloat162float(h));
    }
}

// V[b, s, h*64+d] (fp32) -> Vt hi/lo [bh][d][s] (bf16)
__global__ void vtrans_split(const float* __restrict__ V,
                             bf16* __restrict__ th, bf16* __restrict__ tl)
{
    __shared__ float t[32][33];
    const int bh = blockIdx.z, b = bh >> 4, h = bh & 15;
    const int s0 = blockIdx.x * 32, d0 = blockIdx.y * 32;
    const float* src = V + ((long long)b * SEQ) * DM + h * DK;
    #pragma unroll
    for (int j = 0; j < 32; j += 8)
        t[threadIdx.y + j][threadIdx.x] =
            src[(long long)(s0 + threadIdx.y + j) * DM + d0 + threadIdx.x];
    __syncthreads();
    const long long base = (long long)bh * DK * SEQ;
    #pragma unroll
    for (int j = 0; j < 32; j += 8) {
        const float v = t[threadIdx.x][threadIdx.y + j];
        bf16 hh = __float2bfloat16(v);
        const long long off = base + (long long)(d0 + threadIdx.y + j) * SEQ + s0 + threadIdx.x;
        th[off] = hh;
        tl[off] = __float2bfloat16(v - __bfloat162float(hh));
    }
}

// ---------------------------------------------------------------------------
// pure-bf16 projection GEMM: C[M,1024] = A[M,K] @ B[1024,K]^T, pre-split hi/lo.
// BM=BN=128, chunk = 64 k. 256 threads / 8 warps (wm 2 x wn 4), 2-stage cp.async.
// EPI: 0 = fp32 C, 2 = fp32 C + bias, 3 = per-head split bf16 (for Q,K)
// ---------------------------------------------------------------------------
template<int EPI>
__global__ __launch_bounds__(256, 1) void pgemm(
    const bf16* __restrict__ Ah, const bf16* __restrict__ Al,
    const bf16* __restrict__ Bh, const bf16* __restrict__ Bl,
    float* __restrict__ Cf, bf16* __restrict__ Ch, bf16* __restrict__ Cl,
    const float* __restrict__ bias, int K, int ldc)
{
    extern __shared__ char smp[];
    constexpr int AST = 72;                // bf16 units (144 B rows, pad vs conflicts)
    constexpr int TSZ = 128 * 144;         // 18432 B per sub-tile
    constexpr int STG_SZ = 4 * TSZ;        // Ah|Al|Bh|Bl per stage

    const int tid = threadIdx.x, lane = tid & 31, wid = tid >> 5;
    const int wm0 = (wid & 1) * 64, wn0 = (wid >> 1) * 32;
    const int m0 = blockIdx.y * 128, n0 = blockIdx.x * 128;
    const uint32_t sb = smem_u32(smp);
    const int NC = K >> 6;

    auto issue = [&](int kt) {
        const uint32_t st = sb + (kt & 1) * STG_SZ;
        const long long kof = (long long)kt * 64;
        #pragma unroll
        for (int i = 0; i < 4; ++i) {
            const int c = tid + i * 256, row = c >> 3, col = c & 7;
            const uint32_t d = st + row * 144 + col * 16;
            const long long sA = (long long)(m0 + row) * K + kof + col * 8;
            const long long sB = (long long)(n0 + row) * K + kof + col * 8;
            CP16(d,           Ah + sA);
            CP16(d + TSZ,     Al + sA);
            CP16(d + 2 * TSZ, Bh + sB);
            CP16(d + 3 * TSZ, Bl + sB);
        }
        CPCOMMIT();
    };

    float acc[4][4][4] = {};
    const int frow = lane & 15, fk8 = (lane >> 4) * 8;

    issue(0);
    if (NC > 1) issue(1);
    for (int kt = 0; kt < NC; ++kt) {
        if (kt + 1 < NC) CPWAIT(1); else CPWAIT(0);
        __syncthreads();
        const uint32_t st = sb + (kt & 1) * STG_SZ;
        #pragma unroll
        for (int kq = 0; kq < 4; ++kq) {
            uint32_t ah[4][4], al[4][4], bh2[2][4], bl2[2][4];
            #pragma unroll
            for (int mg = 0; mg < 4; ++mg) {
                const uint32_t off = ((wm0 + mg * 16 + frow) * AST + kq * 16 + fk8) * 2;
                LDSM4(ah[mg], st + off);
                LDSM4(al[mg], st + TSZ + off);
            }
            #pragma unroll
            for (int nn = 0; nn < 2; ++nn) {
                const uint32_t off = ((wn0 + nn * 16 + frow) * AST + kq * 16 + fk8) * 2;
                LDSM4(bh2[nn], st + 2 * TSZ + off);
                LDSM4(bl2[nn], st + 3 * TSZ + off);
            }
            #pragma unroll
            for (int mg = 0; mg < 4; ++mg)
                #pragma unroll
                for (int nn = 0; nn < 2; ++nn)
                    #pragma unroll
                    for (int g = 0; g < 2; ++g)
                        MMA_BF16(acc[mg][nn * 2 + g], ah[mg], bh2[nn][g], bh2[nn][g + 2]);
            #pragma unroll
            for (int mg = 0; mg < 4; ++mg)
                #pragma unroll
                for (int nn = 0; nn < 2; ++nn)
                    #pragma unroll
                    for (int g = 0; g < 2; ++g)
                        MMA_BF16(acc[mg][nn * 2 + g], ah[mg], bl2[nn][g], bl2[nn][g + 2]);
            #pragma unroll
            for (int mg = 0; mg < 4; ++mg)
                #pragma unroll
                for (int nn = 0; nn < 2; ++nn)
                    #pragma unroll
                    for (int g = 0; g < 2; ++g)
                        MMA_BF16(acc[mg][nn * 2 + g], al[mg], bh2[nn][g], bh2[nn][g + 2]);
        }
        __syncthreads();
        if (kt + 2 < NC) issue(kt + 2);
    }

    #pragma unroll
    for (int mg = 0; mg < 4; ++mg) {
        const int row = m0 + wm0 + mg * 16 + (lane >> 2);
        #pragma unroll
        for (int n8 = 0; n8 < 4; ++n8) {
            const int col = n0 + wn0 + n8 * 8 + (lane & 3) * 2;
            float v0 = acc[mg][n8][0], v1 = acc[mg][n8][1];
            float v2 = acc[mg][n8][2], v3 = acc[mg][n8][3];
            if (EPI == 2) {
                const float b0 = bias[col], b1 = bias[col + 1];
                v0 += b0; v1 += b1; v2 += b0; v3 += b1;
            }
            if (EPI == 3) {
                const int bh = ((row >> 11) << 4) + (col >> 6);
                const int s = row & 2047, d = col & 63;
                const size_t off = ((size_t)bh * SEQ + s) * DK + d;
                uint32_t H, L;
                split2(v0, v1, H, L);
                *reinterpret_cast<uint32_t*>(Ch + off) = H;
                *reinterpret_cast<uint32_t*>(Cl + off) = L;
                split2(v2, v3, H, L);
                *reinterpret_cast<uint32_t*>(Ch + off + 8 * DK) = H;
                *reinterpret_cast<uint32_t*>(Cl + off + 8 * DK) = L;
            } else {
                *reinterpret_cast<float2*>(Cf + (long long)row * ldc + col) =
                    make_float2(v0, v1);
                *reinterpret_cast<float2*>(Cf + (long long)(row + 8) * ldc + col) =
                    make_float2(v2, v3);
            }
        }
    }
}

// ---------------------------------------------------------------------------
// fused attention: per (bh, q-tile 128): loop 16 k-tiles of 128:
//   S = Q@K^T (3-pass bf16) -> sigmoid -> STG A -> in-reg A-frags -> H += S@V^T
// warps: wm 0..3 (32 S-rows), wn 0..1 (64 S-cols = split-k half for H)
// ---------------------------------------------------------------------------
__global__ __launch_bounds__(256, 1) void fused_attn(
    const bf16* __restrict__ Qh, const bf16* __restrict__ Ql,
    const bf16* __restrict__ Kh, const bf16* __restrict__ Kl,
    const bf16* __restrict__ Vh, const bf16* __restrict__ Vl,
    float* __restrict__ Aout, bf16* __restrict__ Hh, bf16* __restrict__ Hl)
{
    extern __shared__ char smf[];
    constexpr int KT   = 144;              // K/Q smem row bytes (64 bf16 + pad)
    constexpr int VT   = 272;              // Vt smem row bytes (128 bf16 + pad)
    constexpr int QSZ  = 128 * KT;         // 18432
    constexpr int KSZ  = 128 * KT;
    constexpr int VSZ  = 64 * VT;          // 17408
    constexpr int BUF0 = 2 * QSZ;          // 36864: buffers after Qhi|Qlo
    constexpr int BUFS = 2 * KSZ + 2 * VSZ;// 71680 per stage
    constexpr int NT   = SEQ / 128;        // 16

    const int tid = threadIdx.x, lane = tid & 31, wid = tid >> 5;
    const int wm = wid & 3, wn = wid >> 2;
    const int bh = blockIdx.y, b = bh >> 4, h = bh & 15;
    const int q0 = blockIdx.x * 128;
    const uint32_t sb = smem_u32(smf);
    const int frow = lane & 15, fk8 = (lane >> 4) * 8;

    const bf16* Qhg = Qh + ((size_t)bh * SEQ + q0) * DK;
    const bf16* Qlg = Ql + ((size_t)bh * SEQ + q0) * DK;

    // Q tile (once)
    #pragma unroll
    for (int i = 0; i < 4; ++i) {
        const int c = tid + i * 256, row = c >> 3, col = c & 7;
        CP16(sb + row * KT + col * 16,       Qhg + row * DK + col * 8);
        CP16(sb + QSZ + row * KT + col * 16, Qlg + row * DK + col * 8);
    }
    CPCOMMIT();

    auto issue = [&](int kt) {
        const uint32_t st = sb + BUF0 + (kt & 1) * BUFS;
        const bf16* khg = Kh + ((size_t)bh * SEQ + kt * 128) * DK;
        const bf16* klg = Kl + ((size_t)bh * SEQ + kt * 128) * DK;
        #pragma unroll
        for (int i = 0; i < 4; ++i) {
            const int c = tid + i * 256, row = c >> 3, col = c & 7;
            CP16(st + row * KT + col * 16,       khg + row * DK + col * 8);
            CP16(st + KSZ + row * KT + col * 16, klg + row * DK + col * 8);
        }
        const bf16* vhg = Vh + (size_t)bh * DK * SEQ + kt * 128;
        const bf16* vlg = Vl + (size_t)bh * DK * SEQ + kt * 128;
        #pragma unroll
        for (int i = 0; i < 4; ++i) {
            const int c = tid + i * 256, row = c >> 4, col = c & 15;
            CP16(st + 2 * KSZ + row * VT + col * 16,       vhg + (size_t)row * SEQ + col * 8);
            CP16(st + 2 * KSZ + VSZ + row * VT + col * 16, vlg + (size_t)row * SEQ + col * 8);
        }
        CPCOMMIT();
    };
    issue(0);
    issue(1);

    float accH[2][8][4] = {};
    float* Abase = Aout + (size_t)bh * SEQ * SEQ;

    for (int kt = 0; kt < NT; ++kt) {
        if (kt + 1 < NT) CPWAIT(1); else CPWAIT(0);
        __syncthreads();
        const uint32_t st = sb + BUF0 + (kt & 1) * BUFS;

        // ---- S = Q @ K^T (3-pass) ----
        float accS[2][8][4] = {};
        #pragma unroll
        for (int kq = 0; kq < 4; ++kq) {
            uint32_t qh2[2][4], ql2[2][4], kh2[4][4], kl2[4][4];
            #pragma unroll
            for (int mg = 0; mg < 2; ++mg) {
                const uint32_t off = ((wm * 32 + mg * 16 + frow) * 72 + kq * 16 + fk8) * 2;
                LDSM4(qh2[mg], sb + off);
                LDSM4(ql2[mg], sb + QSZ + off);
            }
            #pragma unroll
            for (int nn = 0; nn < 4; ++nn) {
                const uint32_t off = ((wn * 64 + nn * 16 + frow) * 72 + kq * 16 + fk8) * 2;
                LDSM4(kh2[nn], st + off);
                LDSM4(kl2[nn], st + KSZ + off);
            }
            #pragma unroll
            for (int mg = 0; mg < 2; ++mg)
                #pragma unroll
                for (int nn = 0; nn < 4; ++nn)
                    #pragma unroll
                    for (int g = 0; g < 2; ++g)
                        MMA_BF16(accS[mg][nn * 2 + g], qh2[mg], kh2[nn][g], kh2[nn][g + 2]);
            #pragma unroll
            for (int mg = 0; mg < 2; ++mg)
                #pragma unroll
                for (int nn = 0; nn < 4; ++nn)
                    #pragma unroll
                    for (int g = 0; g < 2; ++g)
                        MMA_BF16(accS[mg][nn * 2 + g], qh2[mg], kl2[nn][g], kl2[nn][g + 2]);
            #pragma unroll
            for (int mg = 0; mg < 2; ++mg)
                #pragma unroll
                for (int nn = 0; nn < 4; ++nn)
                    #pragma unroll
                    for (int g = 0; g < 2; ++g)
                        MMA_BF16(accS[mg][nn * 2 + g], ql2[mg], kh2[nn][g], kh2[nn][g + 2]);
        }

        // ---- sigmoid + write A + build in-register A-fragments ----
        #pragma unroll
        for (int mg = 0; mg < 2; ++mg)
            #pragma unroll
            for (int n8 = 0; n8 < 8; ++n8)
                #pragma unroll
                for (int e = 0; e < 4; ++e)
                    accS[mg][n8][e] =
                        1.0f / (1.0f + __expf(-0.125f * accS[mg][n8][e]));

        #pragma unroll
        for (int mg = 0; mg < 2; ++mg) {
            const int rl = wm * 32 + mg * 16 + (lane >> 2);
            #pragma unroll
            for (int n8 = 0; n8 < 8; ++n8) {
                const int colg = kt * 128 + wn * 64 + n8 * 8 + (lane & 3) * 2;
                *reinterpret_cast<float2*>(Abase + (size_t)(q0 + rl) * SEQ + colg) =
                    make_float2(accS[mg][n8][0], accS[mg][n8][1]);
                *reinterpret_cast<float2*>(Abase + (size_t)(q0 + rl + 8) * SEQ + colg) =
                    make_float2(accS[mg][n8][2], accS[mg][n8][3]);
            }
        }

        uint32_t ah2[2][4][4], al2[2][4][4];
        #pragma unroll
        for (int mg = 0; mg < 2; ++mg)
            #pragma unroll
            for (int j = 0; j < 4; ++j) {
                split2(accS[mg][2 * j][0],     accS[mg][2 * j][1],     ah2[mg][j][0], al2[mg][j][0]);
                split2(accS[mg][2 * j][2],     accS[mg][2 * j][3],     ah2[mg][j][1], al2[mg][j][1]);
                split2(accS[mg][2 * j + 1][0], accS[mg][2 * j + 1][1], ah2[mg][j][2], al2[mg][j][2]);
                split2(accS[mg][2 * j + 1][2], accS[mg][2 * j + 1][3], ah2[mg][j][3], al2[mg][j][3]);
            }

        // ---- H += S @ V^T over this warp's 64-col k-slice ----
        #pragma unroll
        for (int j = 0; j < 4; ++j) {
            uint32_t vh2[4][4];
            #pragma unroll
            for (int vn = 0; vn < 4; ++vn) {
                const uint32_t off = ((vn * 16 + frow) * 136 + wn * 64 + j * 16 + fk8) * 2;
                LDSM4(vh2[vn], st + 2 * KSZ + off);
            }
            #pragma unroll
            for (int mg = 0; mg < 2; ++mg)
                #pragma unroll
                for (int vn = 0; vn < 4; ++vn)
                    #pragma unroll
                    for (int g = 0; g < 2; ++g)
                        MMA_BF16(accH[mg][vn * 2 + g], ah2[mg][j], vh2[vn][g], vh2[vn][g + 2]);
            #pragma unroll
            for (int mg = 0; mg < 2; ++mg)
                #pragma unroll
                for (int vn = 0; vn < 4; ++vn)
                    #pragma unroll
                    for (int g = 0; g < 2; ++g)
                        MMA_BF16(accH[mg][vn * 2 + g], al2[mg][j], vh2[vn][g], vh2[vn][g + 2]);
            uint32_t vl2[4][4];
            #pragma unroll
            for (int vn = 0; vn < 4; ++vn) {
                const uint32_t off = ((vn * 16 + frow) * 136 + wn * 64 + j * 16 + fk8) * 2;
                LDSM4(vl2[vn], st + 2 * KSZ + VSZ + off);
            }
            #pragma unroll
            for (int mg = 0; mg < 2; ++mg)
                #pragma unroll
                for (int vn = 0; vn < 4; ++vn)
                    #pragma unroll
                    for (int g = 0; g < 2; ++g)
                        MMA_BF16(accH[mg][vn * 2 + g], ah2[mg][j], vl2[vn][g], vl2[vn][g + 2]);
        }

        __syncthreads();
        if (kt + 2 < NT) issue(kt + 2);
    }

    // ---- split-k reduce (wn=1 into wn=0) + write Hc hi/lo ----
    __syncthreads();
    float* red = reinterpret_cast<float*>(smf);   // 128 x 66 fp32 (Q area reused)
    if (wn == 1) {
        #pragma unroll
        for (int mg = 0; mg < 2; ++mg) {
            const int rl = wm * 32 + mg * 16 + (lane >> 2);
            #pragma unroll
            for (int n8 = 0; n8 < 8; ++n8) {
                const int col = n8 * 8 + (lane & 3) * 2;
                *reinterpret_cast<float2*>(&red[(size_t)rl * 66 + col]) =
                    make_float2(accH[mg][n8][0], accH[mg][n8][1]);
                *reinterpret_cast<float2*>(&red[(size_t)(rl + 8) * 66 + col]) =
                    make_float2(accH[mg][n8][2], accH[mg][n8][3]);
            }
        }
    }
    __syncthreads();
    if (wn == 0) {
        #pragma unroll
        for (int mg = 0; mg < 2; ++mg) {
            const int rl = wm * 32 + mg * 16 + (lane >> 2);
            #pragma unroll
            for (int n8 = 0; n8 < 8; ++n8) {
                const int col = n8 * 8 + (lane & 3) * 2;
                const float2 p0 = *reinterpret_cast<float2*>(&red[(size_t)rl * 66 + col]);
                const float2 p1 = *reinterpret_cast<float2*>(&red[(size_t)(rl + 8) * 66 + col]);
                const float v0 = accH[mg][n8][0] + p0.x, v1 = accH[mg][n8][1] + p0.y;
                const float v2 = accH[mg][n8][2] + p1.x, v3 = accH[mg][n8][3] + p1.y;
                const size_t off = ((size_t)(b * SEQ + q0 + rl)) * DM + h * DK + col;
                uint32_t H, L;
                split2(v0, v1, H, L);
                *reinterpret_cast<uint32_t*>(Hh + off) = H;
                *reinterpret_cast<uint32_t*>(Hl + off) = L;
                split2(v2, v3, H, L);
                *reinterpret_cast<uint32_t*>(Hh + off + 8 * DM) = H;
                *reinterpret_cast<uint32_t*>(Hl + off + 8 * DM) = L;
            }
        }
    }
}

// ---------------------------------------------------------------------------
extern "C" void kernel_launch(void* const* d_in, const int* in_sizes, int n_in,
                              void* d_out, int out_size)
{
    (void)in_sizes; (void)n_in; (void)out_size;
    const float* Xq = (const float*)d_in[0];
    const float* Xk = (const float*)d_in[1];
    const float* Xv = (const float*)d_in[2];
    const float* Wq = (const float*)d_in[3];
    const float* Wk = (const float*)d_in[4];
    const float* Wv = (const float*)d_in[5];
    const float* Wh = (const float*)d_in[6];
    const float* bh = (const float*)d_in[7];

    float* out  = (float*)d_out;
    float* Aout = out + (size_t)MTOT * DM;

    float* vp;   cudaGetSymbolAddress((void**)&vp,  g_V);
    bf16 *xh, *xl, *wh, *wl, *qh, *ql, *kh, *kl, *vth, *vtl, *hh, *hl;
    cudaGetSymbolAddress((void**)&xh,  g_Xh);
    cudaGetSymbolAddress((void**)&xl,  g_Xl);
    cudaGetSymbolAddress((void**)&wh,  g_Wh);
    cudaGetSymbolAddress((void**)&wl,  g_Wl);
    cudaGetSymbolAddress((void**)&qh,  g_Qh);
    cudaGetSymbolAddress((void**)&ql,  g_Ql);
    cudaGetSymbolAddress((void**)&kh,  g_Kh);
    cudaGetSymbolAddress((void**)&kl,  g_Kl);
    cudaGetSymbolAddress((void**)&vth, g_Vth);
    cudaGetSymbolAddress((void**)&vtl, g_Vtl);
    cudaGetSymbolAddress((void**)&hh,  g_Hh);
    cudaGetSymbolAddress((void**)&hl,  g_Hl);

    const size_t XN = (size_t)MTOT * DM, WN = (size_t)DM * DM;
    const int smP = 2 * 4 * 128 * 144;                         // 147456
    const int smF = 2 * 128 * 144 + 2 * (2 * 128 * 144 + 2 * 64 * 272);  // 180224
    cudaFuncSetAttribute(pgemm<0>, cudaFuncAttributeMaxDynamicSharedMemorySize, smP);
    cudaFuncSetAttribute(pgemm<2>, cudaFuncAttributeMaxDynamicSharedMemorySize, smP);
    cudaFuncSetAttribute(pgemm<3>, cudaFuncAttributeMaxDynamicSharedMemorySize, smP);
    cudaFuncSetAttribute(fused_attn, cudaFuncAttributeMaxDynamicSharedMemorySize, smF);

    const dim3 tb(32, 8);
    // weight transpose + split
    transpose_split<<<dim3(32, 32), tb>>>(Wq, wh + 0 * WN, wl + 0 * WN, DM);
    transpose_split<<<dim3(32, 32), tb>>>(Wk, wh + 1 * WN, wl + 1 * WN, DM);
    transpose_split<<<dim3(32, 32), tb>>>(Wv, wh + 2 * WN, wl + 2 * WN, DM);
    transpose_split<<<dim3(32, 32), tb>>>(Wh, wh + 3 * WN, wl + 3 * WN, DM);
    // input split
    split_x<<<4096, 256>>>((const float4*)Xq, (uint2*)(xh + 0 * XN), (uint2*)(xl + 0 * XN));
    split_x<<<4096, 256>>>((const float4*)Xk, (uint2*)(xh + 1 * XN), (uint2*)(xl + 1 * XN));
    split_x<<<4096, 256>>>((const float4*)Xv, (uint2*)(xh + 2 * XN), (uint2*)(xl + 2 * XN));

    // projections
    const dim3 gP(DM / 128, MTOT / 128);
    pgemm<3><<<gP, 256, smP>>>(xh + 0 * XN, xl + 0 * XN, wh + 0 * WN, wl + 0 * WN,
                               nullptr, qh, ql, nullptr, DM, DM);
    pgemm<3><<<gP, 256, smP>>>(xh + 1 * XN, xl + 1 * XN, wh + 1 * WN, wl + 1 * WN,
                               nullptr, kh, kl, nullptr, DM, DM);
    pgemm<0><<<gP, 256, smP>>>(xh + 2 * XN, xl + 2 * XN, wh + 2 * WN, wl + 2 * WN,
                               vp, nullptr, nullptr, nullptr, DM, DM);
    // V transpose + split
    vtrans_split<<<dim3(SEQ / 32, DK / 32, NBH), tb>>>(vp, vth, vtl);

    // fused attention (writes A and Hc hi/lo)
    fused_attn<<<dim3(SEQ / 128, NBH), 256, smF>>>(qh, ql, kh, kl, vth, vtl,
                                                   Aout, hh, hl);

    // output projection
    pgemm<2><<<gP, 256, smP>>>(hh, hl, wh + 3 * WN, wl + 3 * WN,
                               out, nullptr, nullptr, bh, DM, DM);
}

// round 6
// speedup vs baseline: 5.7691x; 2.7818x over previous
#include <cuda_runtime.h>
#include <cuda_fp16.h>
#include <cstdint>

#define NHEADS 16
#define DK     64
#define DM     1024
#define NB     2
#define SEQ    2048
#define MTOT   (NB*SEQ)   /* 4096 */
#define NBH    (NB*NHEADS)

typedef __half fp16;

// scratch (__device__ globals; no allocs allowed)
static __device__ float g_V [(size_t)MTOT*DM];          // V fp32 (pre-transpose)
static __device__ fp16  g_X [3][(size_t)MTOT*DM];       // X fp16 (q,k,v)
static __device__ fp16  g_W [4][(size_t)DM*DM];         // W^T fp16 (q,k,v,hidden)
static __device__ fp16  g_Q [(size_t)NBH*SEQ*DK];
static __device__ fp16  g_K [(size_t)NBH*SEQ*DK];
static __device__ fp16  g_Vt[(size_t)NBH*DK*SEQ];       // V^T per (b,h): [dk][seq]
static __device__ fp16  g_H [(size_t)MTOT*DM];          // Hc fp16

// ---------------------------------------------------------------------------
__device__ __forceinline__ uint32_t smem_u32(const void* p) {
    uint32_t a;
    asm("{ .reg .u64 t; cvta.to.shared.u64 t, %1; cvt.u32.u64 %0, t; }"
        : "=r"(a) : "l"(p));
    return a;
}
#define CP16(dst, src) \
    asm volatile("cp.async.cg.shared.global [%0], [%1], 16;" \
        :: "r"(dst), "l"(src) : "memory")
#define CPCOMMIT() asm volatile("cp.async.commit_group;" ::: "memory")
#define CPWAIT(n)  asm volatile("cp.async.wait_group %0;" :: "n"(n) : "memory")

#define LDSM4(d, addr) \
    asm volatile("ldmatrix.sync.aligned.m8n8.x4.shared.b16 {%0,%1,%2,%3}, [%4];" \
        : "=r"((d)[0]), "=r"((d)[1]), "=r"((d)[2]), "=r"((d)[3]) : "r"(addr))

#define MMA_FP16(c, a, b0v, b1v) \
    asm volatile("mma.sync.aligned.m16n8k16.row.col.f32.f16.f16.f32 " \
        "{%0,%1,%2,%3},{%4,%5,%6,%7},{%8,%9},{%0,%1,%2,%3};" \
        : "+f"((c)[0]), "+f"((c)[1]), "+f"((c)[2]), "+f"((c)[3]) \
        : "r"((a)[0]), "r"((a)[1]), "r"((a)[2]), "r"((a)[3]), "r"(b0v), "r"(b1v))

__device__ __forceinline__ uint32_t pack2(float a, float b) {
    __half2 h = __floats2half2_rn(a, b);   // a -> low, b -> high
    return *reinterpret_cast<uint32_t*>(&h);
}
__device__ __forceinline__ float sigm(float v) {
    return __fdividef(1.0f, 1.0f + __expf(-0.125f * v));
}

// ---------------------------------------------------------------------------
// prep kernels
// ---------------------------------------------------------------------------
__global__ void cvt_x(const float4* __restrict__ src, uint2* __restrict__ dst)
{
    const int i = blockIdx.x * 256 + threadIdx.x;
    const float4 v = src[i];
    dst[i] = make_uint2(pack2(v.x, v.y), pack2(v.z, v.w));
}

__global__ void transpose_cvt(const float* __restrict__ src, fp16* __restrict__ dst, int N)
{
    __shared__ float t[32][33];
    int x = blockIdx.x * 32 + threadIdx.x;
    int y = blockIdx.y * 32 + threadIdx.y;
    #pragma unroll
    for (int j = 0; j < 32; j += 8)
        t[threadIdx.y + j][threadIdx.x] = src[(long long)(y + j) * N + x];
    __syncthreads();
    x = blockIdx.y * 32 + threadIdx.x;
    y = blockIdx.x * 32 + threadIdx.y;
    #pragma unroll
    for (int j = 0; j < 32; j += 8)
        dst[(long long)(y + j) * N + x] = __float2half_rn(t[threadIdx.x][threadIdx.y + j]);
}

// V[b, s, h*64+d] (fp32) -> Vt [bh][d][s] (fp16)
__global__ void vtrans_cvt(const float* __restrict__ V, fp16* __restrict__ dst)
{
    __shared__ float t[32][33];
    const int bh = blockIdx.z, b = bh >> 4, h = bh & 15;
    const int s0 = blockIdx.x * 32, d0 = blockIdx.y * 32;
    const float* src = V + ((long long)b * SEQ) * DM + h * DK;
    #pragma unroll
    for (int j = 0; j < 32; j += 8)
        t[threadIdx.y + j][threadIdx.x] =
            src[(long long)(s0 + threadIdx.y + j) * DM + d0 + threadIdx.x];
    __syncthreads();
    const long long base = (long long)bh * DK * SEQ;
    #pragma unroll
    for (int j = 0; j < 32; j += 8)
        dst[base + (long long)(d0 + threadIdx.y + j) * SEQ + s0 + threadIdx.x] =
            __float2half_rn(t[threadIdx.x][threadIdx.y + j]);
}

// ---------------------------------------------------------------------------
// fp16 projection GEMM: C[M,1024] = A[M,1024] @ B[1024,1024]^T  (K = 1024)
// BM=BN=128, chunk 64 k. 256 threads / 8 warps (wm 2 x wn 4), 2-stage cp.async.
// EPI: 0 = fp32 C, 2 = fp32 C + bias, 3 = per-head fp16 (Q,K)
// ---------------------------------------------------------------------------
template<int EPI>
__global__ __launch_bounds__(256, 2) void pgemm(
    const fp16* __restrict__ A, const fp16* __restrict__ B,
    float* __restrict__ Cf, fp16* __restrict__ Ch,
    const float* __restrict__ bias)
{
    extern __shared__ char smp[];
    constexpr int TSZ = 128 * 144;         // bytes per tile (row = 128B + 16 pad)
    constexpr int STG = 2 * TSZ;           // A|B per stage

    const int tid = threadIdx.x, lane = tid & 31, wid = tid >> 5;
    const int wm0 = (wid & 1) * 64, wn0 = (wid >> 1) * 32;
    const int m0 = blockIdx.y * 128, n0 = blockIdx.x * 128;
    const uint32_t sb = smem_u32(smp);

    auto issue = [&](int kt) {
        const uint32_t st = sb + (kt & 1) * STG;
        const long long kof = (long long)kt * 64;
        #pragma unroll
        for (int i = 0; i < 4; ++i) {
            const int c = tid + i * 256, row = c >> 3, col = c & 7;
            const uint32_t d = st + row * 144 + col * 16;
            CP16(d,       A + (long long)(m0 + row) * DM + kof + col * 8);
            CP16(d + TSZ, B + (long long)(n0 + row) * DM + kof + col * 8);
        }
        CPCOMMIT();
    };

    float acc[4][4][4] = {};
    const int frow = lane & 15, fk8 = (lane >> 4) * 8;

    issue(0);
    issue(1);
    for (int kt = 0; kt < 16; ++kt) {
        if (kt < 15) CPWAIT(1); else CPWAIT(0);
        __syncthreads();
        const uint32_t st = sb + (kt & 1) * STG;
        #pragma unroll
        for (int kq = 0; kq < 4; ++kq) {
            uint32_t af[4][4], bf2[2][4];
            #pragma unroll
            for (int mg = 0; mg < 4; ++mg) {
                const uint32_t off = ((wm0 + mg * 16 + frow) * 72 + kq * 16 + fk8) * 2;
                LDSM4(af[mg], st + off);
            }
            #pragma unroll
            for (int nn = 0; nn < 2; ++nn) {
                const uint32_t off = ((wn0 + nn * 16 + frow) * 72 + kq * 16 + fk8) * 2;
                LDSM4(bf2[nn], st + TSZ + off);
            }
            #pragma unroll
            for (int mg = 0; mg < 4; ++mg)
                #pragma unroll
                for (int nn = 0; nn < 2; ++nn)
                    #pragma unroll
                    for (int g = 0; g < 2; ++g)
                        MMA_FP16(acc[mg][nn * 2 + g], af[mg], bf2[nn][g], bf2[nn][g + 2]);
        }
        __syncthreads();
        if (kt + 2 < 16) issue(kt + 2);
    }

    #pragma unroll
    for (int mg = 0; mg < 4; ++mg) {
        const int row = m0 + wm0 + mg * 16 + (lane >> 2);
        #pragma unroll
        for (int n8 = 0; n8 < 4; ++n8) {
            const int col = n0 + wn0 + n8 * 8 + (lane & 3) * 2;
            float v0 = acc[mg][n8][0], v1 = acc[mg][n8][1];
            float v2 = acc[mg][n8][2], v3 = acc[mg][n8][3];
            if (EPI == 2) {
                const float b0 = bias[col], b1 = bias[col + 1];
                v0 += b0; v1 += b1; v2 += b0; v3 += b1;
            }
            if (EPI == 3) {
                const int bh = ((row >> 11) << 4) + (col >> 6);
                const int s = row & 2047, d = col & 63;
                const size_t off = ((size_t)bh * SEQ + s) * DK + d;
                *reinterpret_cast<uint32_t*>(Ch + off)          = pack2(v0, v1);
                *reinterpret_cast<uint32_t*>(Ch + off + 8 * DK) = pack2(v2, v3);
            } else {
                *reinterpret_cast<float2*>(Cf + (long long)row * DM + col) =
                    make_float2(v0, v1);
                *reinterpret_cast<float2*>(Cf + (long long)(row + 8) * DM + col) =
                    make_float2(v2, v3);
            }
        }
    }
}

// ---------------------------------------------------------------------------
// fused attention: per (bh, q-tile 128): loop 16 k-tiles of 128:
//   S = Q@K^T -> sigmoid -> STG A -> in-reg A-frags -> H += S@V^T
// warps: wm 0..3 (32 S-rows), wn 0..1 (64 S-cols = split-k half for H)
// ---------------------------------------------------------------------------
__global__ __launch_bounds__(256, 1) void fused_attn(
    const fp16* __restrict__ Q, const fp16* __restrict__ K,
    const fp16* __restrict__ Vt,
    float* __restrict__ Aout, fp16* __restrict__ Hp)
{
    extern __shared__ char smf[];
    constexpr int KT   = 144;               // K/Q smem row bytes
    constexpr int VT   = 272;               // Vt smem row bytes
    constexpr int QSZ  = 128 * KT;          // 18432
    constexpr int KSZ  = 128 * KT;
    constexpr int VSZ  = 64 * VT;           // 17408
    constexpr int BUFS = KSZ + VSZ;         // 35840 per stage
    constexpr int NT   = SEQ / 128;         // 16

    const int tid = threadIdx.x, lane = tid & 31, wid = tid >> 5;
    const int wm = wid & 3, wn = wid >> 2;
    const int bh = blockIdx.y, b = bh >> 4, h = bh & 15;
    const int q0 = blockIdx.x * 128;
    const uint32_t sb = smem_u32(smf);
    const int frow = lane & 15, fk8 = (lane >> 4) * 8;

    // Q tile (once): 128 rows x 8 16B-chunks = 1024 chunks
    {
        const fp16* Qg = Q + ((size_t)bh * SEQ + q0) * DK;
        #pragma unroll
        for (int i = 0; i < 4; ++i) {
            const int c = tid + i * 256, row = c >> 3, col = c & 7;
            CP16(sb + row * KT + col * 16, Qg + row * DK + col * 8);
        }
        CPCOMMIT();
    }

    auto issue = [&](int kt) {
        const uint32_t st = sb + QSZ + (kt & 1) * BUFS;
        const fp16* kg = K + ((size_t)bh * SEQ + kt * 128) * DK;
        #pragma unroll
        for (int i = 0; i < 4; ++i) {      // 128 rows x 8 chunks
            const int c = tid + i * 256, row = c >> 3, col = c & 7;
            CP16(st + row * KT + col * 16, kg + row * DK + col * 8);
        }
        const fp16* vg = Vt + (size_t)bh * DK * SEQ + kt * 128;
        #pragma unroll
        for (int i = 0; i < 4; ++i) {      // 64 rows x 16 chunks
            const int c = tid + i * 256, row = c >> 4, col = c & 15;
            CP16(st + KSZ + row * VT + col * 16, vg + (size_t)row * SEQ + col * 8);
        }
        CPCOMMIT();
    };
    issue(0);
    issue(1);

    float accH[2][8][4] = {};
    float* Abase = Aout + (size_t)bh * SEQ * SEQ;

    for (int kt = 0; kt < NT; ++kt) {
        if (kt + 1 < NT) CPWAIT(1); else CPWAIT(0);
        __syncthreads();
        const uint32_t st = sb + QSZ + (kt & 1) * BUFS;

        // ---- S = Q @ K^T ----
        float accS[2][8][4] = {};
        #pragma unroll
        for (int kq = 0; kq < 4; ++kq) {
            uint32_t qf[2][4], kf[4][4];
            #pragma unroll
            for (int mg = 0; mg < 2; ++mg) {
                const uint32_t off = ((wm * 32 + mg * 16 + frow) * 72 + kq * 16 + fk8) * 2;
                LDSM4(qf[mg], sb + off);
            }
            #pragma unroll
            for (int nn = 0; nn < 4; ++nn) {
                const uint32_t off = ((wn * 64 + nn * 16 + frow) * 72 + kq * 16 + fk8) * 2;
                LDSM4(kf[nn], st + off);
            }
            #pragma unroll
            for (int mg = 0; mg < 2; ++mg)
                #pragma unroll
                for (int nn = 0; nn < 4; ++nn)
                    #pragma unroll
                    for (int g = 0; g < 2; ++g)
                        MMA_FP16(accS[mg][nn * 2 + g], qf[mg], kf[nn][g], kf[nn][g + 2]);
        }

        // ---- sigmoid + write A ----
        #pragma unroll
        for (int mg = 0; mg < 2; ++mg)
            #pragma unroll
            for (int n8 = 0; n8 < 8; ++n8)
                #pragma unroll
                for (int e = 0; e < 4; ++e)
                    accS[mg][n8][e] = sigm(accS[mg][n8][e]);

        #pragma unroll
        for (int mg = 0; mg < 2; ++mg) {
            const int rl = wm * 32 + mg * 16 + (lane >> 2);
            #pragma unroll
            for (int n8 = 0; n8 < 8; ++n8) {
                const int colg = kt * 128 + wn * 64 + n8 * 8 + (lane & 3) * 2;
                *reinterpret_cast<float2*>(Abase + (size_t)(q0 + rl) * SEQ + colg) =
                    make_float2(accS[mg][n8][0], accS[mg][n8][1]);
                *reinterpret_cast<float2*>(Abase + (size_t)(q0 + rl + 8) * SEQ + colg) =
                    make_float2(accS[mg][n8][2], accS[mg][n8][3]);
            }
        }

        // ---- in-register A fragments (acc -> A-frag identity) ----
        uint32_t af[2][4][4];
        #pragma unroll
        for (int mg = 0; mg < 2; ++mg)
            #pragma unroll
            for (int j = 0; j < 4; ++j) {
                af[mg][j][0] = pack2(accS[mg][2 * j][0],     accS[mg][2 * j][1]);
                af[mg][j][1] = pack2(accS[mg][2 * j][2],     accS[mg][2 * j][3]);
                af[mg][j][2] = pack2(accS[mg][2 * j + 1][0], accS[mg][2 * j + 1][1]);
                af[mg][j][3] = pack2(accS[mg][2 * j + 1][2], accS[mg][2 * j + 1][3]);
            }

        // ---- H += S @ V^T over this warp's 64-col k-slice ----
        #pragma unroll
        for (int j = 0; j < 4; ++j) {
            uint32_t vf[4][4];
            #pragma unroll
            for (int vn = 0; vn < 4; ++vn) {
                const uint32_t off = ((vn * 16 + frow) * 136 + wn * 64 + j * 16 + fk8) * 2;
                LDSM4(vf[vn], st + KSZ + off);
            }
            #pragma unroll
            for (int mg = 0; mg < 2; ++mg)
                #pragma unroll
                for (int vn = 0; vn < 4; ++vn)
                    #pragma unroll
                    for (int g = 0; g < 2; ++g)
                        MMA_FP16(accH[mg][vn * 2 + g], af[mg][j], vf[vn][g], vf[vn][g + 2]);
        }

        __syncthreads();
        if (kt + 2 < NT) issue(kt + 2);
    }

    // ---- split-k reduce (wn=1 into wn=0) + write Hc fp16 ----
    __syncthreads();
    float* red = reinterpret_cast<float*>(smf);   // 128 x 66 fp32 (tiles dead)
    if (wn == 1) {
        #pragma unroll
        for (int mg = 0; mg < 2; ++mg) {
            const int rl = wm * 32 + mg * 16 + (lane >> 2);
            #pragma unroll
            for (int n8 = 0; n8 < 8; ++n8) {
                const int col = n8 * 8 + (lane & 3) * 2;
                *reinterpret_cast<float2*>(&red[(size_t)rl * 66 + col]) =
                    make_float2(accH[mg][n8][0], accH[mg][n8][1]);
                *reinterpret_cast<float2*>(&red[(size_t)(rl + 8) * 66 + col]) =
                    make_float2(accH[mg][n8][2], accH[mg][n8][3]);
            }
        }
    }
    __syncthreads();
    if (wn == 0) {
        #pragma unroll
        for (int mg = 0; mg < 2; ++mg) {
            const int rl = wm * 32 + mg * 16 + (lane >> 2);
            #pragma unroll
            for (int n8 = 0; n8 < 8; ++n8) {
                const int col = n8 * 8 + (lane & 3) * 2;
                const float2 p0 = *reinterpret_cast<float2*>(&red[(size_t)rl * 66 + col]);
                const float2 p1 = *reinterpret_cast<float2*>(&red[(size_t)(rl + 8) * 66 + col]);
                const size_t off = ((size_t)(b * SEQ + q0 + rl)) * DM + h * DK + col;
                *reinterpret_cast<uint32_t*>(Hp + off) =
                    pack2(accH[mg][n8][0] + p0.x, accH[mg][n8][1] + p0.y);
                *reinterpret_cast<uint32_t*>(Hp + off + 8 * DM) =
                    pack2(accH[mg][n8][2] + p1.x, accH[mg][n8][3] + p1.y);
            }
        }
    }
}

// ---------------------------------------------------------------------------
extern "C" void kernel_launch(void* const* d_in, const int* in_sizes, int n_in,
                              void* d_out, int out_size)
{
    (void)in_sizes; (void)n_in; (void)out_size;
    const float* Xq = (const float*)d_in[0];
    const float* Xk = (const float*)d_in[1];
    const float* Xv = (const float*)d_in[2];
    const float* Wq = (const float*)d_in[3];
    const float* Wk = (const float*)d_in[4];
    const float* Wv = (const float*)d_in[5];
    const float* Wh = (const float*)d_in[6];
    const float* bh = (const float*)d_in[7];

    float* out  = (float*)d_out;
    float* Aout = out + (size_t)MTOT * DM;

    float* vp;
    fp16 *xp, *wp, *qp, *kp, *vtp, *hp;
    cudaGetSymbolAddress((void**)&vp,  g_V);
    cudaGetSymbolAddress((void**)&xp,  g_X);
    cudaGetSymbolAddress((void**)&wp,  g_W);
    cudaGetSymbolAddress((void**)&qp,  g_Q);
    cudaGetSymbolAddress((void**)&kp,  g_K);
    cudaGetSymbolAddress((void**)&vtp, g_Vt);
    cudaGetSymbolAddress((void**)&hp,  g_H);

    const size_t XN = (size_t)MTOT * DM, WN = (size_t)DM * DM;
    const int smP = 2 * 2 * 128 * 144;                       // 73728
    const int smF = 128 * 144 + 2 * (128 * 144 + 64 * 272);  // 90112
    cudaFuncSetAttribute(pgemm<0>, cudaFuncAttributeMaxDynamicSharedMemorySize, smP);
    cudaFuncSetAttribute(pgemm<2>, cudaFuncAttributeMaxDynamicSharedMemorySize, smP);
    cudaFuncSetAttribute(pgemm<3>, cudaFuncAttributeMaxDynamicSharedMemorySize, smP);
    cudaFuncSetAttribute(fused_attn, cudaFuncAttributeMaxDynamicSharedMemorySize, smF);

    const dim3 tb(32, 8);
    // prep: W^T fp16, X fp16
    transpose_cvt<<<dim3(32, 32), tb>>>(Wq, wp + 0 * WN, DM);
    transpose_cvt<<<dim3(32, 32), tb>>>(Wk, wp + 1 * WN, DM);
    transpose_cvt<<<dim3(32, 32), tb>>>(Wv, wp + 2 * WN, DM);
    transpose_cvt<<<dim3(32, 32), tb>>>(Wh, wp + 3 * WN, DM);
    cvt_x<<<4096, 256>>>((const float4*)Xq, (uint2*)(xp + 0 * XN));
    cvt_x<<<4096, 256>>>((const float4*)Xk, (uint2*)(xp + 1 * XN));
    cvt_x<<<4096, 256>>>((const float4*)Xv, (uint2*)(xp + 2 * XN));

    // projections
    const dim3 gP(DM / 128, MTOT / 128);
    pgemm<3><<<gP, 256, smP>>>(xp + 0 * XN, wp + 0 * WN, nullptr, qp, nullptr);
    pgemm<3><<<gP, 256, smP>>>(xp + 1 * XN, wp + 1 * WN, nullptr, kp, nullptr);
    pgemm<0><<<gP, 256, smP>>>(xp + 2 * XN, wp + 2 * WN, vp, nullptr, nullptr);
    vtrans_cvt<<<dim3(SEQ / 32, DK / 32, NBH), tb>>>(vp, vtp);

    // fused attention (writes A fp32 and Hc fp16)
    fused_attn<<<dim3(SEQ / 128, NBH), 256, smF>>>(qp, kp, vtp, Aout, hp);

    // output projection (+bias)
    pgemm<2><<<gP, 256, smP>>>(hp, wp + 3 * WN, out, nullptr, bh);
}

// round 8
// speedup vs baseline: 5.9949x; 1.0391x over previous
#include <cuda_runtime.h>
#include <cuda_fp16.h>
#include <cstdint>

#define NHEADS 16
#define DK     64
#define DM     1024
#define NB     2
#define SEQ    2048
#define MTOT   (NB*SEQ)   /* 4096 */
#define NBH    (NB*NHEADS)

typedef __half fp16;

// scratch (__device__ globals; no allocs allowed)
static __device__ float g_V [(size_t)MTOT*DM];          // V fp32 (pre-transpose)
static __device__ fp16  g_X [3][(size_t)MTOT*DM];       // X fp16 (q,k,v)
static __device__ fp16  g_W [4][(size_t)DM*DM];         // W^T fp16 (q,k,v,hidden)
static __device__ fp16  g_Q [(size_t)NBH*SEQ*DK];
static __device__ fp16  g_K [(size_t)NBH*SEQ*DK];
static __device__ fp16  g_Vt[(size_t)NBH*DK*SEQ];       // V^T per (b,h): [dk][seq]
static __device__ fp16  g_H [(size_t)MTOT*DM];          // Hc fp16

// ---------------------------------------------------------------------------
__device__ __forceinline__ uint32_t smem_u32(const void* p) {
    uint32_t a;
    asm("{ .reg .u64 t; cvta.to.shared.u64 t, %1; cvt.u32.u64 %0, t; }"
        : "=r"(a) : "l"(p));
    return a;
}
#define CP16(dst, src) \
    asm volatile("cp.async.cg.shared.global [%0], [%1], 16;" \
        :: "r"(dst), "l"(src) : "memory")
#define CPCOMMIT() asm volatile("cp.async.commit_group;" ::: "memory")
#define CPWAIT(n)  asm volatile("cp.async.wait_group %0;" :: "n"(n) : "memory")

#define LDSM4(d, addr) \
    asm volatile("ldmatrix.sync.aligned.m8n8.x4.shared.b16 {%0,%1,%2,%3}, [%4];" \
        : "=r"((d)[0]), "=r"((d)[1]), "=r"((d)[2]), "=r"((d)[3]) : "r"(addr))

#define MMA_FP16(c, a, b0v, b1v) \
    asm volatile("mma.sync.aligned.m16n8k16.row.col.f32.f16.f16.f32 " \
        "{%0,%1,%2,%3},{%4,%5,%6,%7},{%8,%9},{%0,%1,%2,%3};" \
        : "+f"((c)[0]), "+f"((c)[1]), "+f"((c)[2]), "+f"((c)[3]) \
        : "r"((a)[0]), "r"((a)[1]), "r"((a)[2]), "r"((a)[3]), "r"(b0v), "r"(b1v))

__device__ __forceinline__ uint32_t pack2(float a, float b) {
    __half2 h = __floats2half2_rn(a, b);   // a -> low, b -> high
    return *reinterpret_cast<uint32_t*>(&h);
}
__device__ __forceinline__ float sigm(float v) {
    return __fdividef(1.0f, 1.0f + __expf(-0.125f * v));
}

// ---------------------------------------------------------------------------
// prep kernels (merged)
// ---------------------------------------------------------------------------
__global__ void cvt_x3(const float4* __restrict__ s0, const float4* __restrict__ s1,
                       const float4* __restrict__ s2, uint2* __restrict__ dst)
{
    const int z = blockIdx.y;
    const float4* src = (z == 0) ? s0 : (z == 1) ? s1 : s2;
    const int i = blockIdx.x * 256 + threadIdx.x;
    const float4 v = src[i];
    dst[(size_t)z * ((size_t)MTOT * DM / 4) + i] =
        make_uint2(pack2(v.x, v.y), pack2(v.z, v.w));
}

__global__ void wtrans4(const float* __restrict__ w0, const float* __restrict__ w1,
                        const float* __restrict__ w2, const float* __restrict__ w3,
                        fp16* __restrict__ dstbase)
{
    __shared__ float t[32][33];
    const int z = blockIdx.z;
    const float* src = (z == 0) ? w0 : (z == 1) ? w1 : (z == 2) ? w2 : w3;
    fp16* dst = dstbase + (size_t)z * DM * DM;
    int x = blockIdx.x * 32 + threadIdx.x;
    int y = blockIdx.y * 32 + threadIdx.y;
    #pragma unroll
    for (int j = 0; j < 32; j += 8)
        t[threadIdx.y + j][threadIdx.x] = src[(long long)(y + j) * DM + x];
    __syncthreads();
    x = blockIdx.y * 32 + threadIdx.x;
    y = blockIdx.x * 32 + threadIdx.y;
    #pragma unroll
    for (int j = 0; j < 32; j += 8)
        dst[(long long)(y + j) * DM + x] = __float2half_rn(t[threadIdx.x][threadIdx.y + j]);
}

// V[b, s, h*64+d] (fp32) -> Vt [bh][d][s] (fp16)
__global__ void vtrans_cvt(const float* __restrict__ V, fp16* __restrict__ dst)
{
    __shared__ float t[32][33];
    const int bh = blockIdx.z, b = bh >> 4, h = bh & 15;
    const int s0 = blockIdx.x * 32, d0 = blockIdx.y * 32;
    const float* src = V + ((long long)b * SEQ) * DM + h * DK;
    #pragma unroll
    for (int j = 0; j < 32; j += 8)
        t[threadIdx.y + j][threadIdx.x] =
            src[(long long)(s0 + threadIdx.y + j) * DM + d0 + threadIdx.x];
    __syncthreads();
    const long long base = (long long)bh * DK * SEQ;
    #pragma unroll
    for (int j = 0; j < 32; j += 8)
        dst[base + (long long)(d0 + threadIdx.y + j) * SEQ + s0 + threadIdx.x] =
            __float2half_rn(t[threadIdx.x][threadIdx.y + j]);
}

// ---------------------------------------------------------------------------
// GEMM core shared by QKV-projection and out-projection.
// C[M,1024] = A[M,1024] @ B[1024,1024]^T. BM=BN=128, chunk 64 k, 8 warps.
// (plain lambdas: defined in device code, no --extended-lambda needed)
// ---------------------------------------------------------------------------
template<typename EpiFn>
__device__ __forceinline__ void gemm_core(
    const fp16* __restrict__ A, const fp16* __restrict__ B,
    int m0, int n0, char* smp, EpiFn epi)
{
    constexpr int TSZ = 128 * 144;
    constexpr int STG = 2 * TSZ;
    const int tid = threadIdx.x, lane = tid & 31, wid = tid >> 5;
    const int wm0 = (wid & 1) * 64, wn0 = (wid >> 1) * 32;
    const uint32_t sb = smem_u32(smp);

    auto issue = [&](int kt) {
        const uint32_t st = sb + (kt & 1) * STG;
        const long long kof = (long long)kt * 64;
        #pragma unroll
        for (int i = 0; i < 4; ++i) {
            const int c = tid + i * 256, row = c >> 3, col = c & 7;
            const uint32_t d = st + row * 144 + col * 16;
            CP16(d,       A + (long long)(m0 + row) * DM + kof + col * 8);
            CP16(d + TSZ, B + (long long)(n0 + row) * DM + kof + col * 8);
        }
        CPCOMMIT();
    };

    float acc[4][4][4] = {};
    const int frow = lane & 15, fk8 = (lane >> 4) * 8;

    issue(0);
    issue(1);
    for (int kt = 0; kt < 16; ++kt) {
        if (kt < 15) CPWAIT(1); else CPWAIT(0);
        __syncthreads();
        const uint32_t st = sb + (kt & 1) * STG;
        #pragma unroll
        for (int kq = 0; kq < 4; ++kq) {
            uint32_t af[4][4], bf2[2][4];
            #pragma unroll
            for (int mg = 0; mg < 4; ++mg) {
                const uint32_t off = ((wm0 + mg * 16 + frow) * 72 + kq * 16 + fk8) * 2;
                LDSM4(af[mg], st + off);
            }
            #pragma unroll
            for (int nn = 0; nn < 2; ++nn) {
                const uint32_t off = ((wn0 + nn * 16 + frow) * 72 + kq * 16 + fk8) * 2;
                LDSM4(bf2[nn], st + TSZ + off);
            }
            #pragma unroll
            for (int mg = 0; mg < 4; ++mg)
                #pragma unroll
                for (int nn = 0; nn < 2; ++nn)
                    #pragma unroll
                    for (int g = 0; g < 2; ++g)
                        MMA_FP16(acc[mg][nn * 2 + g], af[mg], bf2[nn][g], bf2[nn][g + 2]);
        }
        __syncthreads();
        if (kt + 2 < 16) issue(kt + 2);
    }

    #pragma unroll
    for (int mg = 0; mg < 4; ++mg) {
        const int row = m0 + wm0 + mg * 16 + (lane >> 2);
        #pragma unroll
        for (int n8 = 0; n8 < 4; ++n8) {
            const int col = n0 + wn0 + n8 * 8 + (lane & 3) * 2;
            epi(row, col, acc[mg][n8]);
        }
    }
}

// Q/K/V projections in one launch: z = 0 (Q fp16/head), 1 (K fp16/head), 2 (V fp32)
__global__ __launch_bounds__(256, 2) void pgemm_qkv(
    const fp16* __restrict__ X, const fp16* __restrict__ W,
    fp16* __restrict__ Qp, fp16* __restrict__ Kp, float* __restrict__ Vp)
{
    extern __shared__ char smp[];
    const int z = blockIdx.z;
    const fp16* A = X + (size_t)z * MTOT * DM;
    const fp16* B = W + (size_t)z * DM * DM;
    const int m0 = blockIdx.y * 128, n0 = blockIdx.x * 128;
    if (z == 2) {
        gemm_core(A, B, m0, n0, smp,
            [&](int row, int col, float* v) {
                *reinterpret_cast<float2*>(Vp + (long long)row * DM + col) =
                    make_float2(v[0], v[1]);
                *reinterpret_cast<float2*>(Vp + (long long)(row + 8) * DM + col) =
                    make_float2(v[2], v[3]);
            });
    } else {
        fp16* Ch = (z == 0) ? Qp : Kp;
        gemm_core(A, B, m0, n0, smp,
            [&](int row, int col, float* v) {
                const int bh = ((row >> 11) << 4) + (col >> 6);
                const int s = row & 2047, d = col & 63;
                const size_t off = ((size_t)bh * SEQ + s) * DK + d;
                *reinterpret_cast<uint32_t*>(Ch + off)          = pack2(v[0], v[1]);
                *reinterpret_cast<uint32_t*>(Ch + off + 8 * DK) = pack2(v[2], v[3]);
            });
    }
}

// out-projection (+bias)
__global__ __launch_bounds__(256, 2) void pgemm_out(
    const fp16* __restrict__ A, const fp16* __restrict__ B,
    float* __restrict__ Cf, const float* __restrict__ bias)
{
    extern __shared__ char smp[];
    const int m0 = blockIdx.y * 128, n0 = blockIdx.x * 128;
    gemm_core(A, B, m0, n0, smp,
        [&](int row, int col, float* v) {
            const float b0 = bias[col], b1 = bias[col + 1];
            *reinterpret_cast<float2*>(Cf + (long long)row * DM + col) =
                make_float2(v[0] + b0, v[1] + b1);
            *reinterpret_cast<float2*>(Cf + (long long)(row + 8) * DM + col) =
                make_float2(v[2] + b0, v[3] + b1);
        });
}

// ---------------------------------------------------------------------------
// fused attention: per (bh, q-tile 128): loop 16 k-tiles of 128 (3-stage pipe):
//   S = Q@K^T -> sigmoid -> STG A -> in-reg A-frags -> H += S@V^T
// warps: wm 0..3 (32 S-rows), wn 0..1 (64 S-cols = split-k half for H)
// ---------------------------------------------------------------------------
__global__ __launch_bounds__(256, 1) void fused_attn(
    const fp16* __restrict__ Q, const fp16* __restrict__ K,
    const fp16* __restrict__ Vt,
    float* __restrict__ Aout, fp16* __restrict__ Hp)
{
    extern __shared__ char smf[];
    constexpr int KT   = 144;               // K/Q smem row bytes
    constexpr int VT   = 272;               // Vt smem row bytes
    constexpr int QSZ  = 128 * KT;          // 18432
    constexpr int KSZ  = 128 * KT;
    constexpr int VSZ  = 64 * VT;           // 17408
    constexpr int BUFS = KSZ + VSZ;         // 35840 per stage
    constexpr int NT   = SEQ / 128;         // 16

    const int tid = threadIdx.x, lane = tid & 31, wid = tid >> 5;
    const int wm = wid & 3, wn = wid >> 2;
    const int bh = blockIdx.y, b = bh >> 4, h = bh & 15;
    const int q0 = blockIdx.x * 128;
    const uint32_t sb = smem_u32(smf);
    const int frow = lane & 15, fk8 = (lane >> 4) * 8;

    // Q tile (once): 128 rows x 8 16B-chunks = 1024 chunks
    {
        const fp16* Qg = Q + ((size_t)bh * SEQ + q0) * DK;
        #pragma unroll
        for (int i = 0; i < 4; ++i) {
            const int c = tid + i * 256, row = c >> 3, col = c & 7;
            CP16(sb + row * KT + col * 16, Qg + row * DK + col * 8);
        }
        CPCOMMIT();
    }

    auto issue = [&](int kt) {
        const uint32_t st = sb + QSZ + (kt % 3) * BUFS;
        const fp16* kg = K + ((size_t)bh * SEQ + kt * 128) * DK;
        #pragma unroll
        for (int i = 0; i < 4; ++i) {      // 128 rows x 8 chunks
            const int c = tid + i * 256, row = c >> 3, col = c & 7;
            CP16(st + row * KT + col * 16, kg + row * DK + col * 8);
        }
        const fp16* vg = Vt + (size_t)bh * DK * SEQ + kt * 128;
        #pragma unroll
        for (int i = 0; i < 4; ++i) {      // 64 rows x 16 chunks
            const int c = tid + i * 256, row = c >> 4, col = c & 15;
            CP16(st + KSZ + row * VT + col * 16, vg + (size_t)row * SEQ + col * 8);
        }
        CPCOMMIT();
    };
    issue(0);
    issue(1);
    issue(2);

    float accH[2][8][4] = {};
    float* Abase = Aout + (size_t)bh * SEQ * SEQ;

    for (int kt = 0; kt < NT; ++kt) {
        if (kt + 2 < NT)      CPWAIT(2);
        else if (kt + 1 < NT) CPWAIT(1);
        else                  CPWAIT(0);
        __syncthreads();
        const uint32_t st = sb + QSZ + (kt % 3) * BUFS;

        // ---- S = Q @ K^T ----
        float accS[2][8][4] = {};
        #pragma unroll
        for (int kq = 0; kq < 4; ++kq) {
            uint32_t qf[2][4], kf[4][4];
            #pragma unroll
            for (int mg = 0; mg < 2; ++mg) {
                const uint32_t off = ((wm * 32 + mg * 16 + frow) * 72 + kq * 16 + fk8) * 2;
                LDSM4(qf[mg], sb + off);
            }
            #pragma unroll
            for (int nn = 0; nn < 4; ++nn) {
                const uint32_t off = ((wn * 64 + nn * 16 + frow) * 72 + kq * 16 + fk8) * 2;
                LDSM4(kf[nn], st + off);
            }
            #pragma unroll
            for (int mg = 0; mg < 2; ++mg)
                #pragma unroll
                for (int nn = 0; nn < 4; ++nn)
                    #pragma unroll
                    for (int g = 0; g < 2; ++g)
                        MMA_FP16(accS[mg][nn * 2 + g], qf[mg], kf[nn][g], kf[nn][g + 2]);
        }

        // ---- sigmoid + write A ----
        #pragma unroll
        for (int mg = 0; mg < 2; ++mg)
            #pragma unroll
            for (int n8 = 0; n8 < 8; ++n8)
                #pragma unroll
                for (int e = 0; e < 4; ++e)
                    accS[mg][n8][e] = sigm(accS[mg][n8][e]);

        #pragma unroll
        for (int mg = 0; mg < 2; ++mg) {
            const int rl = wm * 32 + mg * 16 + (lane >> 2);
            #pragma unroll
            for (int n8 = 0; n8 < 8; ++n8) {
                const int colg = kt * 128 + wn * 64 + n8 * 8 + (lane & 3) * 2;
                *reinterpret_cast<float2*>(Abase + (size_t)(q0 + rl) * SEQ + colg) =
                    make_float2(accS[mg][n8][0], accS[mg][n8][1]);
                *reinterpret_cast<float2*>(Abase + (size_t)(q0 + rl + 8) * SEQ + colg) =
                    make_float2(accS[mg][n8][2], accS[mg][n8][3]);
            }
        }

        // ---- in-register A fragments (acc -> A-frag identity) ----
        uint32_t af[2][4][4];
        #pragma unroll
        for (int mg = 0; mg < 2; ++mg)
            #pragma unroll
            for (int j = 0; j < 4; ++j) {
                af[mg][j][0] = pack2(accS[mg][2 * j][0],     accS[mg][2 * j][1]);
                af[mg][j][1] = pack2(accS[mg][2 * j][2],     accS[mg][2 * j][3]);
                af[mg][j][2] = pack2(accS[mg][2 * j + 1][0], accS[mg][2 * j + 1][1]);
                af[mg][j][3] = pack2(accS[mg][2 * j + 1][2], accS[mg][2 * j + 1][3]);
            }

        // ---- H += S @ V^T over this warp's 64-col k-slice ----
        #pragma unroll
        for (int j = 0; j < 4; ++j) {
            uint32_t vf[4][4];
            #pragma unroll
            for (int vn = 0; vn < 4; ++vn) {
                const uint32_t off = ((vn * 16 + frow) * 136 + wn * 64 + j * 16 + fk8) * 2;
                LDSM4(vf[vn], st + KSZ + off);
            }
            #pragma unroll
            for (int mg = 0; mg < 2; ++mg)
                #pragma unroll
                for (int vn = 0; vn < 4; ++vn)
                    #pragma unroll
                    for (int g = 0; g < 2; ++g)
                        MMA_FP16(accH[mg][vn * 2 + g], af[mg][j], vf[vn][g], vf[vn][g + 2]);
        }

        __syncthreads();
        if (kt + 3 < NT) issue(kt + 3);
    }

    // ---- split-k reduce (wn=1 into wn=0) + write Hc fp16 ----
    __syncthreads();
    float* red = reinterpret_cast<float*>(smf);   // 128 x 66 fp32 (tiles dead)
    if (wn == 1) {
        #pragma unroll
        for (int mg = 0; mg < 2; ++mg) {
            const int rl = wm * 32 + mg * 16 + (lane >> 2);
            #pragma unroll
            for (int n8 = 0; n8 < 8; ++n8) {
                const int col = n8 * 8 + (lane & 3) * 2;
                *reinterpret_cast<float2*>(&red[(size_t)rl * 66 + col]) =
                    make_float2(accH[mg][n8][0], accH[mg][n8][1]);
                *reinterpret_cast<float2*>(&red[(size_t)(rl + 8) * 66 + col]) =
                    make_float2(accH[mg][n8][2], accH[mg][n8][3]);
            }
        }
    }
    __syncthreads();
    if (wn == 0) {
        #pragma unroll
        for (int mg = 0; mg < 2; ++mg) {
            const int rl = wm * 32 + mg * 16 + (lane >> 2);
            #pragma unroll
            for (int n8 = 0; n8 < 8; ++n8) {
                const int col = n8 * 8 + (lane & 3) * 2;
                const float2 p0 = *reinterpret_cast<float2*>(&red[(size_t)rl * 66 + col]);
                const float2 p1 = *reinterpret_cast<float2*>(&red[(size_t)(rl + 8) * 66 + col]);
                const size_t off = ((size_t)(b * SEQ + q0 + rl)) * DM + h * DK + col;
                *reinterpret_cast<uint32_t*>(Hp + off) =
                    pack2(accH[mg][n8][0] + p0.x, accH[mg][n8][1] + p0.y);
                *reinterpret_cast<uint32_t*>(Hp + off + 8 * DM) =
                    pack2(accH[mg][n8][2] + p1.x, accH[mg][n8][3] + p1.y);
            }
        }
    }
}

// ---------------------------------------------------------------------------
extern "C" void kernel_launch(void* const* d_in, const int* in_sizes, int n_in,
                              void* d_out, int out_size)
{
    (void)in_sizes; (void)n_in; (void)out_size;
    const float* Xq = (const float*)d_in[0];
    const float* Xk = (const float*)d_in[1];
    const float* Xv = (const float*)d_in[2];
    const float* Wq = (const float*)d_in[3];
    const float* Wk = (const float*)d_in[4];
    const float* Wv = (const float*)d_in[5];
    const float* Wh = (const float*)d_in[6];
    const float* bh = (const float*)d_in[7];

    float* out  = (float*)d_out;
    float* Aout = out + (size_t)MTOT * DM;

    float* vp;
    fp16 *xp, *wp, *qp, *kp, *vtp, *hp;
    cudaGetSymbolAddress((void**)&vp,  g_V);
    cudaGetSymbolAddress((void**)&xp,  g_X);
    cudaGetSymbolAddress((void**)&wp,  g_W);
    cudaGetSymbolAddress((void**)&qp,  g_Q);
    cudaGetSymbolAddress((void**)&kp,  g_K);
    cudaGetSymbolAddress((void**)&vtp, g_Vt);
    cudaGetSymbolAddress((void**)&hp,  g_H);

    const size_t WN = (size_t)DM * DM;
    const int smP = 2 * 2 * 128 * 144;                       // 73728
    const int smF = 128 * 144 + 3 * (128 * 144 + 64 * 272);  // 125952
    cudaFuncSetAttribute(pgemm_qkv, cudaFuncAttributeMaxDynamicSharedMemorySize, smP);
    cudaFuncSetAttribute(pgemm_out, cudaFuncAttributeMaxDynamicSharedMemorySize, smP);
    cudaFuncSetAttribute(fused_attn, cudaFuncAttributeMaxDynamicSharedMemorySize, smF);

    // prep: W^T fp16 (one launch), X fp16 (one launch)
    wtrans4<<<dim3(32, 32, 4), dim3(32, 8)>>>(Wq, Wk, Wv, Wh, wp);
    cvt_x3<<<dim3(4096, 3), 256>>>((const float4*)Xq, (const float4*)Xk,
                                   (const float4*)Xv, (uint2*)xp);

    // Q/K/V projections in one launch
    pgemm_qkv<<<dim3(DM / 128, MTOT / 128, 3), 256, smP>>>(xp, wp, qp, kp, vp);
    vtrans_cvt<<<dim3(SEQ / 32, DK / 32, NBH), dim3(32, 8)>>>(vp, vtp);

    // fused attention (writes A fp32 and Hc fp16)
    fused_attn<<<dim3(SEQ / 128, NBH), 256, smF>>>(qp, kp, vtp, Aout, hp);

    // output projection (+bias)
    pgemm_out<<<dim3(DM / 128, MTOT / 128), 256, smP>>>(hp, wp + 3 * WN, out, bh);
}